// round 3
// baseline (speedup 1.0000x reference)
#include <cuda_runtime.h>
#include <cstddef>

#define N_ROWS 131072
#define K_CODES 1024
#define D_DIM 128

// ---- scratch (no cudaMalloc allowed; written ONLY from device code) ----
__device__ int   g_idx[N_ROWS];
__device__ float g_enorm[K_CODES];
__device__ float g_cnorm[N_ROWS];
__device__ float g_lossPartial[N_ROWS / 128];

// ============================================================
// Row sum-of-squares replicating XLA-GPU row-reduction:
// warp per row, lane l sums squares of consecutive elements
// [4l..4l+3] sequentially, then shfl-down tree 16,8,4,2,1.
// All ops via __fmul_rn/__fadd_rn (no fma contraction).
// Two kernels so the __device__ destination is referenced from
// device code only (host-side &__device__ symbol is invalid).
// ============================================================
__device__ __forceinline__ float row_sumsq(const float* __restrict__ src,
                                           int w, int lane) {
    float4 v = reinterpret_cast<const float4*>(src + (size_t)w * D_DIM)[lane];
    float s = __fmul_rn(v.x, v.x);
    s = __fadd_rn(s, __fmul_rn(v.y, v.y));
    s = __fadd_rn(s, __fmul_rn(v.z, v.z));
    s = __fadd_rn(s, __fmul_rn(v.w, v.w));
    #pragma unroll
    for (int o = 16; o > 0; o >>= 1)
        s = __fadd_rn(s, __shfl_down_sync(0xffffffffu, s, o));
    return s;
}

__global__ void enorm_kernel(const float* __restrict__ E) {
    int w    = (int)((blockIdx.x * (size_t)blockDim.x + threadIdx.x) >> 5);
    int lane = threadIdx.x & 31;
    if (w >= K_CODES) return;
    float s = row_sumsq(E, w, lane);
    if (lane == 0) g_enorm[w] = s;
}

__global__ void cnorm_kernel(const float* __restrict__ X) {
    int w    = (int)((blockIdx.x * (size_t)blockDim.x + threadIdx.x) >> 5);
    int lane = threadIdx.x & 31;
    if (w >= N_ROWS) return;
    float s = row_sumsq(X, w, lane);
    if (lane == 0) g_cnorm[w] = s;
}

// ============================================================
// Fused distance-GEMM + fp32-quantized argmin + loss partial.
// BM=128 rows/block, 8 tiles of BN=128 codes, full D=128 in smem.
// 256 threads, 8x8 register micro-tile. Ascending-k fma chain
// matches cuBLAS/Eigen accumulation. Epilogue replicates
//   d = fl( fl(cn + en) - 2*dot )   (2*dot exact)
// with first-index tie-break on the quantized d.
// ============================================================
__global__ void __launch_bounds__(256, 1)
argmin_kernel(const float* __restrict__ X, const float* __restrict__ E) {
    extern __shared__ float smem[];
    float* Xs = smem;                 // [128][128], Xs[d*128 + m]
    float* Es = smem + 128 * 128;     // [128][128], Es[d*128 + n]

    const int tid = threadIdx.x;
    const int tx  = tid & 15;         // code coordinate (8 codes each)
    const int ty  = tid >> 4;         // row coordinate (8 rows each)
    const int rowBase = blockIdx.x * 128;

    // ---- load X tile transposed ----
    #pragma unroll
    for (int it = 0; it < 16; ++it) {
        int lin = tid + 256 * it;            // 0..4095
        int d4  = (lin >> 7) << 2;
        int m   = lin & 127;
        float4 v = reinterpret_cast<const float4*>(
            X + (size_t)(rowBase + m) * D_DIM)[d4 >> 2];
        Xs[(d4 + 0) * 128 + m] = v.x;
        Xs[(d4 + 1) * 128 + m] = v.y;
        Xs[(d4 + 2) * 128 + m] = v.z;
        Xs[(d4 + 3) * 128 + m] = v.w;
    }

    // per-row |x|^2 (reference-rounded bits from cnorm_kernel)
    float cn[8];
    #pragma unroll
    for (int i = 0; i < 8; i++) cn[i] = g_cnorm[rowBase + ty * 8 + i];

    float best[8];
    int   bidx[8];
    #pragma unroll
    for (int i = 0; i < 8; i++) { best[i] = 3.4e38f; bidx[i] = 0; }

    for (int t = 0; t < 8; ++t) {
        __syncthreads();  // protect Es before overwrite
        // ---- load E tile transposed ----
        #pragma unroll
        for (int it = 0; it < 16; ++it) {
            int lin = tid + 256 * it;
            int d4  = (lin >> 7) << 2;
            int n   = lin & 127;
            float4 v = reinterpret_cast<const float4*>(
                E + (size_t)(t * 128 + n) * D_DIM)[d4 >> 2];
            Es[(d4 + 0) * 128 + n] = v.x;
            Es[(d4 + 1) * 128 + n] = v.y;
            Es[(d4 + 2) * 128 + n] = v.z;
            Es[(d4 + 3) * 128 + n] = v.w;
        }
        __syncthreads();

        float acc[8][8];
        #pragma unroll
        for (int i = 0; i < 8; i++)
            #pragma unroll
            for (int j = 0; j < 8; j++) acc[i][j] = 0.f;

        // ascending-d single-accumulator fma chain (cuBLAS/Eigen order)
        #pragma unroll 4
        for (int d = 0; d < 128; ++d) {
            float4 xa = *reinterpret_cast<const float4*>(&Xs[d * 128 + ty * 8]);
            float4 xb = *reinterpret_cast<const float4*>(&Xs[d * 128 + ty * 8 + 4]);
            float4 ea = *reinterpret_cast<const float4*>(&Es[d * 128 + tx * 8]);
            float4 eb = *reinterpret_cast<const float4*>(&Es[d * 128 + tx * 8 + 4]);
            float xv[8] = {xa.x, xa.y, xa.z, xa.w, xb.x, xb.y, xb.z, xb.w};
            float ev[8] = {ea.x, ea.y, ea.z, ea.w, eb.x, eb.y, eb.z, eb.w};
            #pragma unroll
            for (int i = 0; i < 8; i++)
                #pragma unroll
                for (int j = 0; j < 8; j++)
                    acc[i][j] = fmaf(xv[i], ev[j], acc[i][j]);
        }

        // ---- reference-rounded distance + argmin (k ascending per thread) ----
        #pragma unroll
        for (int j = 0; j < 8; j++) {
            int k = t * 128 + tx * 8 + j;
            float en = g_enorm[k];
            #pragma unroll
            for (int i = 0; i < 8; i++) {
                float t1 = __fadd_rn(cn[i], en);                        // fl(|x|^2+|e|^2)
                float d  = __fadd_rn(t1, -__fmul_rn(2.0f, acc[i][j]));  // fl(t1-2dot)
                if (d < best[i]) { best[i] = d; bidx[i] = k; }
            }
        }
    }

    // ---- cross-thread argmin reduction (smallest-index tie-break) ----
    __syncthreads();
    float* redS = Es;                               // [128][16]
    int*   redI = (int*)(Es + 128 * 16);            // [128][16]
    #pragma unroll
    for (int i = 0; i < 8; i++) {
        int m = ty * 8 + i;
        redS[m * 16 + tx] = best[i];
        redI[m * 16 + tx] = bidx[i];
    }
    __syncthreads();

    float dmin = 0.f;
    if (tid < 128) {
        int m = tid;
        float myMin = redS[m * 16];
        int   myIdx = redI[m * 16];
        #pragma unroll
        for (int q = 1; q < 16; q++) {
            float s  = redS[m * 16 + q];
            int   k2 = redI[m * 16 + q];
            if (s < myMin || (s == myMin && k2 < myIdx)) { myMin = s; myIdx = k2; }
        }
        dmin = myMin;                       // min_k ||x - e_k||^2 (ref-rounded)
        g_idx[rowBase + m] = myIdx;
    }
    __syncthreads();

    // ---- deterministic block loss partial ----
    float* rsum = Es;
    if (tid < 128) rsum[tid] = dmin;
    __syncthreads();
    for (int off = 64; off > 0; off >>= 1) {
        if (tid < off) rsum[tid] += rsum[tid + off];
        __syncthreads();
    }
    if (tid == 0) g_lossPartial[blockIdx.x] = rsum[0];
}

// ============================================================
// loss = 1.25 * sum(dmin) / (N*D)   (q_loss == e_loss in value)
// ============================================================
__global__ void loss_kernel(float* __restrict__ out) {
    __shared__ float sm[256];
    float s = 0.f;
    for (int i = threadIdx.x; i < N_ROWS / 128; i += 256) s += g_lossPartial[i];
    sm[threadIdx.x] = s;
    __syncthreads();
    for (int off = 128; off > 0; off >>= 1) {
        if (threadIdx.x < off) sm[threadIdx.x] += sm[threadIdx.x + off];
        __syncthreads();
    }
    if (threadIdx.x == 0)
        out[0] = sm[0] * (1.25f / ((float)N_ROWS * (float)D_DIM));
}

// ============================================================
// quantized_st = fl(c + fl(e[idx] - c)) (STE rounding emulated)
// plus one-hot encodings. Warp per row, coalesced scalar stores
// (output base misaligned for vectors: loss occupies d_out[0]).
// ============================================================
__global__ void __launch_bounds__(256)
writer_kernel(const float* __restrict__ X, const float* __restrict__ E,
              float* __restrict__ out) {
    int warp = (int)((blockIdx.x * (size_t)blockDim.x + threadIdx.x) >> 5);
    int lane = threadIdx.x & 31;
    if (warp >= N_ROWS) return;
    int idx = g_idx[warp];

    const float* er = E + (size_t)idx * D_DIM;
    const float* xr = X + (size_t)warp * D_DIM;
    float* q = out + 1 + (size_t)warp * D_DIM;
    #pragma unroll
    for (int i = 0; i < 4; i++) {
        int d = lane + 32 * i;
        float c = xr[d];
        float e = er[d];
        q[d] = __fadd_rn(c, __fadd_rn(e, -c));
    }

    float* enc = out + 1 + (size_t)N_ROWS * D_DIM + (size_t)warp * K_CODES;
    #pragma unroll
    for (int i = 0; i < 32; i++) {
        int k = lane + 32 * i;
        enc[k] = (k == idx) ? 1.0f : 0.0f;
    }
}

// ============================================================
extern "C" void kernel_launch(void* const* d_in, const int* in_sizes, int n_in,
                              void* d_out, int out_size) {
    const float* X = (const float*)d_in[0];   // c_input [N, D]
    const float* E = (const float*)d_in[1];   // embedding_weight [K, D]
    float* out = (float*)d_out;               // [loss | quantized_st | encodings]

    cudaFuncSetAttribute(argmin_kernel,
                         cudaFuncAttributeMaxDynamicSharedMemorySize, 131072);

    enorm_kernel<<<K_CODES * 32 / 256, 256>>>(E);
    cnorm_kernel<<<N_ROWS * 32 / 256, 256>>>(X);
    argmin_kernel<<<N_ROWS / 128, 256, 131072>>>(X, E);
    loss_kernel<<<1, 256>>>(out);
    writer_kernel<<<N_ROWS / 8, 256>>>(X, E, out);
}

// round 9
// speedup vs baseline: 1.1128x; 1.1128x over previous
#include <cuda_runtime.h>
#include <cuda_bf16.h>
#include <cstddef>
#include <cstdint>

#define N_ROWS 131072
#define K_CODES 1024
#define D_DIM 128
#define TAU 2e-3f    // >= 2x worst-case approx gap-error bound (~1e-3)
#define FLAG_CAP 32768

#define AS_STRIDE_B 784               // A row stride bytes (392 bf16, pad 8)
#define SM_A_BYTES  (128 * AS_STRIDE_B)          // 100352
#define BS_STRIDE_B 144               // B chunk row stride bytes (72 bf16, pad 8)
#define SM_B_OFF    SM_A_BYTES
#define SM_B_BYTES  (128 * BS_STRIDE_B)          // 18432
#define SM_TOTAL    (SM_B_OFF + 2 * SM_B_BYTES)  // 137216

// ---- scratch (device-only access) ----
__device__ int   g_idx[N_ROWS];
__device__ float g_enorm[K_CODES];
__device__ float g_cnorm[N_ROWS];
__device__ float g_lossPartial[N_ROWS / 128];
__device__ int   g_flagCount;
__device__ int   g_flagRows[FLAG_CAP];
// B' image: [n][384] bf16 = [b1(128) | b2(128) | b1(128)] per code
__device__ __align__(16) __nv_bfloat16 g_B[K_CODES * 384];

// ============================================================
// helpers
// ============================================================
__device__ __forceinline__ uint32_t smem_u32(const void* p) {
    uint32_t a;
    asm("{ .reg .u64 t; cvta.to.shared.u64 t, %1; cvt.u32.u64 %0, t; }" : "=r"(a) : "l"(p));
    return a;
}
__device__ __forceinline__ void cp16(uint32_t dst, const void* src) {
    asm volatile("cp.async.ca.shared.global [%0], [%1], 16;" :: "r"(dst), "l"(src) : "memory");
}
__device__ __forceinline__ void cp_commit() { asm volatile("cp.async.commit_group;" ::: "memory"); }
__device__ __forceinline__ void ldsm_x4(uint32_t& r0, uint32_t& r1, uint32_t& r2, uint32_t& r3,
                                        uint32_t addr) {
    asm volatile("ldmatrix.sync.aligned.m8n8.x4.shared.b16 {%0,%1,%2,%3}, [%4];"
        : "=r"(r0), "=r"(r1), "=r"(r2), "=r"(r3) : "r"(addr));
}
__device__ __forceinline__ void ldsm_x2(uint32_t& r0, uint32_t& r1, uint32_t addr) {
    asm volatile("ldmatrix.sync.aligned.m8n8.x2.shared.b16 {%0,%1}, [%2];"
        : "=r"(r0), "=r"(r1) : "r"(addr));
}
__device__ __forceinline__ void mma16816(float* c, const uint32_t* a, const uint32_t* b) {
    asm volatile("mma.sync.aligned.m16n8k16.row.col.f32.bf16.bf16.f32 "
        "{%0,%1,%2,%3}, {%4,%5,%6,%7}, {%8,%9}, {%0,%1,%2,%3};"
        : "+f"(c[0]), "+f"(c[1]), "+f"(c[2]), "+f"(c[3])
        : "r"(a[0]), "r"(a[1]), "r"(a[2]), "r"(a[3]), "r"(b[0]), "r"(b[1]));
}
__device__ __forceinline__ uint32_t pack2(float x, float y, uint32_t& lo) {
    __nv_bfloat16 hx = __float2bfloat16(x), hy = __float2bfloat16(y);
    __nv_bfloat16 lx = __float2bfloat16(x - __bfloat162float(hx));
    __nv_bfloat16 ly = __float2bfloat16(y - __bfloat162float(hy));
    lo = (uint32_t)__bfloat16_as_ushort(lx) | ((uint32_t)__bfloat16_as_ushort(ly) << 16);
    return (uint32_t)__bfloat16_as_ushort(hx) | ((uint32_t)__bfloat16_as_ushort(hy) << 16);
}

// ============================================================
// norms (bitwise-matching XLA warp row-reduce) + flag reset
// ============================================================
__device__ __forceinline__ float row_sumsq(const float* __restrict__ src, int w, int lane) {
    float4 v = reinterpret_cast<const float4*>(src + (size_t)w * D_DIM)[lane];
    float s = __fmul_rn(v.x, v.x);
    s = __fadd_rn(s, __fmul_rn(v.y, v.y));
    s = __fadd_rn(s, __fmul_rn(v.z, v.z));
    s = __fadd_rn(s, __fmul_rn(v.w, v.w));
    #pragma unroll
    for (int o = 16; o > 0; o >>= 1)
        s = __fadd_rn(s, __shfl_down_sync(0xffffffffu, s, o));
    return s;
}
__global__ void enorm_kernel(const float* __restrict__ E) {
    if (blockIdx.x == 0 && threadIdx.x == 0) g_flagCount = 0;
    int w = (int)((blockIdx.x * (size_t)blockDim.x + threadIdx.x) >> 5);
    int lane = threadIdx.x & 31;
    if (w >= K_CODES) return;
    float s = row_sumsq(E, w, lane);
    if (lane == 0) g_enorm[w] = s;
}
__global__ void cnorm_kernel(const float* __restrict__ X) {
    int w = (int)((blockIdx.x * (size_t)blockDim.x + threadIdx.x) >> 5);
    int lane = threadIdx.x & 31;
    if (w >= N_ROWS) return;
    float s = row_sumsq(X, w, lane);
    if (lane == 0) g_cnorm[w] = s;
}

// ============================================================
// B' prep: per code n, [b1 | b2 | b1], k-contiguous
// ============================================================
__global__ void eprep_kernel(const float* __restrict__ E) {
    int p = blockIdx.x * blockDim.x + threadIdx.x;   // pair id
    if (p >= K_CODES * 64) return;
    int n = p >> 6, cp = (p & 63) * 2;
    float2 v = *reinterpret_cast<const float2*>(E + (size_t)n * D_DIM + cp);
    uint32_t lo, hi = pack2(v.x, v.y, lo);
    uint32_t* row = reinterpret_cast<uint32_t*>(g_B + (size_t)n * 384);
    row[(cp) >> 1]       = hi;
    row[(128 + cp) >> 1] = lo;
    row[(256 + cp) >> 1] = hi;
}

// ============================================================
// Main mma.sync argmin kernel.
// 256 thr, 128 rows/CTA, K_eff=384 (a1b1 + a1b2 + a2b1).
// warp grid 2(M)x4(N), warp tile 64x32, 8 N-tiles of 128 codes.
// ============================================================
__global__ void __launch_bounds__(256, 1)
mma_argmin_kernel(const float* __restrict__ X) {
    extern __shared__ char sm[];
    const uint32_t smb = smem_u32(sm);
    const int tid = threadIdx.x;
    const int w = tid >> 5, lane = tid & 31;
    const int wm = w & 1, wn = w >> 1;
    const int tg = lane >> 2, tig = lane & 3;
    const int rowBase = blockIdx.x * 128;

    // ---- build A' = [a1 | a1 | a2] in smem (padded stride) ----
    for (int p = tid; p < 128 * 64; p += 256) {
        int m = p >> 6, cp = (p & 63) * 2;
        float2 v = *reinterpret_cast<const float2*>(X + (size_t)(rowBase + m) * D_DIM + cp);
        uint32_t lo, hi = pack2(v.x, v.y, lo);
        char* rp = sm + (size_t)m * AS_STRIDE_B;
        *reinterpret_cast<uint32_t*>(rp + cp * 2)         = hi;
        *reinterpret_cast<uint32_t*>(rp + (128 + cp) * 2) = hi;
        *reinterpret_cast<uint32_t*>(rp + (256 + cp) * 2) = lo;
    }

    // per-owned-row |x|^2
    float cn[4][2];
    #pragma unroll
    for (int mt = 0; mt < 4; ++mt)
        #pragma unroll
        for (int h = 0; h < 2; ++h)
            cn[mt][h] = g_cnorm[rowBase + wm * 64 + mt * 16 + tg + h * 8];

    float m1[4][2], m2[4][2];
    int   i1[4][2];
    #pragma unroll
    for (int mt = 0; mt < 4; ++mt)
        #pragma unroll
        for (int h = 0; h < 2; ++h) { m1[mt][h] = 3.4e38f; m2[mt][h] = 3.4e38f; i1[mt][h] = 0; }

    float acc[4][4][4];
    #pragma unroll
    for (int mt = 0; mt < 4; ++mt)
        #pragma unroll
        for (int nt = 0; nt < 4; ++nt)
            #pragma unroll
            for (int q = 0; q < 4; ++q) acc[mt][nt][q] = 0.f;

    // chunk loader: chunk c covers codes [NT*128,+128), k [kc*64,+64)
    auto load_chunk = [&](int buf, int c) {
        int NT = c / 6, kc = c % 6;
        uint32_t dbase = smb + SM_B_OFF + (uint32_t)buf * SM_B_BYTES;
        const char* gb = reinterpret_cast<const char*>(g_B);
        for (int i = tid; i < 1024; i += 256) {
            int n = i >> 3, seg = i & 7;
            cp16(dbase + (uint32_t)n * BS_STRIDE_B + seg * 16,
                 gb + (size_t)(NT * 128 + n) * 768 + kc * 128 + seg * 16);
        }
    };

    load_chunk(0, 0); cp_commit();
    load_chunk(1, 1); cp_commit();

    for (int c = 0; c < 48; ++c) {
        const int kc = c % 6, NT = c / 6;
        asm volatile("cp.async.wait_group 1;" ::: "memory");
        __syncthreads();                       // chunk c ready + (first iter) A ready
        const int buf = c & 1;
        const uint32_t bbase = smb + SM_B_OFF + (uint32_t)buf * SM_B_BYTES;

        #pragma unroll
        for (int ks = 0; ks < 4; ++ks) {
            const int kg = kc * 64 + ks * 16;
            uint32_t a[4][4];
            #pragma unroll
            for (int mt = 0; mt < 4; ++mt) {
                int row = wm * 64 + mt * 16 + (lane & 15);
                uint32_t addr = smb + (uint32_t)row * AS_STRIDE_B
                              + (uint32_t)(kg + (lane >> 4) * 8) * 2;
                ldsm_x4(a[mt][0], a[mt][1], a[mt][2], a[mt][3], addr);
            }
            uint32_t b[4][2];
            #pragma unroll
            for (int nt = 0; nt < 4; ++nt) {
                int n = wn * 32 + nt * 8 + (lane & 7);
                int kb = ks * 16 + ((lane >> 3) & 1) * 8;
                ldsm_x2(b[nt][0], b[nt][1],
                        bbase + (uint32_t)n * BS_STRIDE_B + (uint32_t)kb * 2);
            }
            #pragma unroll
            for (int mt = 0; mt < 4; ++mt)
                #pragma unroll
                for (int nt = 0; nt < 4; ++nt)
                    mma16816(acc[mt][nt], a[mt], b[nt]);
        }

        __syncthreads();                       // all warps done reading buf
        if (c + 2 < 48) load_chunk(buf, c + 2);
        cp_commit();

        if (kc == 5) {                         // N-tile NT complete -> epilogue
            float en[4][2];
            const int kbase = NT * 128 + wn * 32;
            #pragma unroll
            for (int nt = 0; nt < 4; ++nt)
                #pragma unroll
                for (int cc = 0; cc < 2; ++cc)
                    en[nt][cc] = g_enorm[kbase + nt * 8 + 2 * tig + cc];
            #pragma unroll
            for (int mt = 0; mt < 4; ++mt)
                #pragma unroll
                for (int h = 0; h < 2; ++h) {
                    float base = cn[mt][h];
                    #pragma unroll
                    for (int nt = 0; nt < 4; ++nt)
                        #pragma unroll
                        for (int cc = 0; cc < 2; ++cc) {
                            float d = fmaf(-2.f, acc[mt][nt][h * 2 + cc], base + en[nt][cc]);
                            int kk = kbase + nt * 8 + 2 * tig + cc;
                            if (d < m1[mt][h]) {
                                m2[mt][h] = m1[mt][h]; m1[mt][h] = d; i1[mt][h] = kk;
                            } else if (d < m2[mt][h]) m2[mt][h] = d;
                        }
                }
            #pragma unroll
            for (int mt = 0; mt < 4; ++mt)
                #pragma unroll
                for (int nt = 0; nt < 4; ++nt)
                    #pragma unroll
                    for (int q = 0; q < 4; ++q) acc[mt][nt][q] = 0.f;
        }
    }

    // ---- cross-thread merge: 16 contributors per row (reuse A region) ----
    // NOTE: no index tie-break needed here: any approx tie gives gap==0 < TAU,
    // so the row is flagged and resolved by the exact (tie-correct) fixup.
    __syncthreads();
    float* redM1 = reinterpret_cast<float*>(sm);          // [128][16]
    float* redM2 = redM1 + 2048;
    int*   redI  = reinterpret_cast<int*>(redM2 + 2048);
    #pragma unroll
    for (int mt = 0; mt < 4; ++mt)
        #pragma unroll
        for (int h = 0; h < 2; ++h) {
            int r = wm * 64 + mt * 16 + tg + h * 8;
            int q = wn * 4 + tig;
            redM1[r * 16 + q] = m1[mt][h];
            redM2[r * 16 + q] = m2[mt][h];
            redI [r * 16 + q] = i1[mt][h];
        }
    __syncthreads();

    float dmin = 0.f;
    if (tid < 128) {
        float M1 = redM1[tid * 16], M2 = redM2[tid * 16];
        int   I  = redI[tid * 16];
        #pragma unroll
        for (int q = 1; q < 16; ++q) {
            float a1v = redM1[tid * 16 + q];
            if (a1v < M1) {
                M2 = fminf(M1, redM2[tid * 16 + q]);
                M1 = a1v;
                I  = redI[tid * 16 + q];
            } else {
                M2 = fminf(M2, a1v);
            }
        }
        int row = rowBase + tid;
        g_idx[row] = I;
        if (M2 - M1 < TAU) {
            int f = atomicAdd(&g_flagCount, 1);
            if (f < FLAG_CAP) g_flagRows[f] = row;
        }
        dmin = M1;
    }
    __syncthreads();

    float* rsum = reinterpret_cast<float*>(sm);
    if (tid < 128) rsum[tid] = dmin;
    __syncthreads();
    for (int off = 64; off > 0; off >>= 1) {
        if (tid < off) rsum[tid] += rsum[tid + off];
        __syncthreads();
    }
    if (tid == 0) g_lossPartial[blockIdx.x] = rsum[0];
}

// ============================================================
// exact fixup for flagged (near-tie) rows: bitwise ref pipeline.
// Reduction carries EXPLICIT index tie-break (jnp.argmin first-min):
// after the first step a left slot can hold a LARGER k than the right,
// so keep-left-on-tie is wrong without comparing indices.
// ============================================================
__global__ void fixup_kernel(const float* __restrict__ X, const float* __restrict__ E) {
    __shared__ float xs[128];
    __shared__ float rv[256];
    __shared__ int   ri[256];
    int nf = g_flagCount;
    if (nf > FLAG_CAP) nf = FLAG_CAP;
    for (int f = blockIdx.x; f < nf; f += gridDim.x) {
        int row = g_flagRows[f];
        if (threadIdx.x < 128) xs[threadIdx.x] = X[(size_t)row * D_DIM + threadIdx.x];
        __syncthreads();
        float cnv = g_cnorm[row];
        float bv = 3.4e38f;
        int   bi = 0;
        #pragma unroll
        for (int k0 = 0; k0 < 4; ++k0) {
            int k = threadIdx.x * 4 + k0;          // ascending per thread
            const float* er = E + (size_t)k * D_DIM;
            float acc = 0.f;
            for (int d = 0; d < D_DIM; ++d) acc = fmaf(xs[d], er[d], acc);
            float t1 = __fadd_rn(cnv, g_enorm[k]);
            float dd = __fadd_rn(t1, -__fmul_rn(2.0f, acc));
            if (dd < bv) { bv = dd; bi = k; }
        }
        rv[threadIdx.x] = bv;
        ri[threadIdx.x] = bi;
        __syncthreads();
        for (int off = 128; off > 0; off >>= 1) {
            if (threadIdx.x < off) {
                float rvr = rv[threadIdx.x + off];
                int   rir = ri[threadIdx.x + off];
                // first-min semantics: smaller value, or equal value + smaller index
                if (rvr < rv[threadIdx.x] ||
                    (rvr == rv[threadIdx.x] && rir < ri[threadIdx.x])) {
                    rv[threadIdx.x] = rvr;
                    ri[threadIdx.x] = rir;
                }
            }
            __syncthreads();
        }
        if (threadIdx.x == 0) g_idx[row] = ri[0];
        __syncthreads();
    }
}

// ============================================================
// loss = 1.25 * sum(dmin) / (N*D)
// ============================================================
__global__ void loss_kernel(float* __restrict__ out) {
    __shared__ float smr[256];
    float s = 0.f;
    for (int i = threadIdx.x; i < N_ROWS / 128; i += 256) s += g_lossPartial[i];
    smr[threadIdx.x] = s;
    __syncthreads();
    for (int off = 128; off > 0; off >>= 1) {
        if (threadIdx.x < off) smr[threadIdx.x] += smr[threadIdx.x + off];
        __syncthreads();
    }
    if (threadIdx.x == 0)
        out[0] = smr[0] * (1.25f / ((float)N_ROWS * (float)D_DIM));
}

// ============================================================
// writer: quantized_st = fl(c + fl(e[idx]-c)) + one-hot encodings
// ============================================================
__global__ void __launch_bounds__(256)
writer_kernel(const float* __restrict__ X, const float* __restrict__ E,
              float* __restrict__ out) {
    int warp = (int)((blockIdx.x * (size_t)blockDim.x + threadIdx.x) >> 5);
    int lane = threadIdx.x & 31;
    if (warp >= N_ROWS) return;
    int idx = g_idx[warp];

    const float* er = E + (size_t)idx * D_DIM;
    const float* xr = X + (size_t)warp * D_DIM;
    float* q = out + 1 + (size_t)warp * D_DIM;
    #pragma unroll
    for (int i = 0; i < 4; i++) {
        int d = lane + 32 * i;
        float c = xr[d];
        float e = er[d];
        q[d] = __fadd_rn(c, __fadd_rn(e, -c));
    }
    float* enc = out + 1 + (size_t)N_ROWS * D_DIM + (size_t)warp * K_CODES;
    #pragma unroll
    for (int i = 0; i < 32; i++) {
        int k = lane + 32 * i;
        enc[k] = (k == idx) ? 1.0f : 0.0f;
    }
}

// ============================================================
extern "C" void kernel_launch(void* const* d_in, const int* in_sizes, int n_in,
                              void* d_out, int out_size) {
    const float* X = (const float*)d_in[0];
    const float* E = (const float*)d_in[1];
    float* out = (float*)d_out;

    cudaFuncSetAttribute(mma_argmin_kernel,
                         cudaFuncAttributeMaxDynamicSharedMemorySize, SM_TOTAL);

    enorm_kernel<<<K_CODES * 32 / 256, 256>>>(E);
    cnorm_kernel<<<N_ROWS * 32 / 256, 256>>>(X);
    eprep_kernel<<<(K_CODES * 64) / 256, 256>>>(E);
    mma_argmin_kernel<<<N_ROWS / 128, 256, SM_TOTAL>>>(X);
    fixup_kernel<<<256, 256>>>(X, E);
    loss_kernel<<<1, 256>>>(out);
    writer_kernel<<<N_ROWS / 8, 256>>>(X, E, out);
}

// round 12
// speedup vs baseline: 1.2752x; 1.1460x over previous
#include <cuda_runtime.h>
#include <cuda_bf16.h>
#include <cstddef>
#include <cstdint>

#define N_ROWS 131072
#define K_CODES 1024
#define D_DIM 128
#define TAU 2e-3f    // >= 2x worst-case approx gap-error bound (~1e-3)
#define FLAG_CAP 32768

#define AS_STRIDE_B 528               // A row stride bytes (256 bf16 + 16B pad)
#define SM_A_BYTES  (128 * AS_STRIDE_B)          // 67584
#define BS_STRIDE_B 272               // B chunk row stride bytes (128 bf16 + 16B pad)
#define SM_B_OFF    SM_A_BYTES
#define SM_B_BYTES  (64 * BS_STRIDE_B)           // 17408
#define SM_TOTAL    (SM_B_OFF + 2 * SM_B_BYTES)  // 102400 -> 2 CTAs/SM

// ---- scratch (device-only access) ----
__device__ int   g_idx[N_ROWS];
__device__ float g_enorm[K_CODES];
__device__ float g_cnorm[N_ROWS];
__device__ float g_lossPartial[N_ROWS / 128];
__device__ int   g_flagCount;
__device__ int   g_flagRows[FLAG_CAP];
// B' image: [n][256] bf16 = [b1(128) | b2(128)] per code (512B/row, L2-resident)
__device__ __align__(16) __nv_bfloat16 g_B[K_CODES * 256];

// ============================================================
// helpers
// ============================================================
__device__ __forceinline__ uint32_t smem_u32(const void* p) {
    uint32_t a;
    asm("{ .reg .u64 t; cvta.to.shared.u64 t, %1; cvt.u32.u64 %0, t; }" : "=r"(a) : "l"(p));
    return a;
}
__device__ __forceinline__ void cp16(uint32_t dst, const void* src) {
    asm volatile("cp.async.ca.shared.global [%0], [%1], 16;" :: "r"(dst), "l"(src) : "memory");
}
__device__ __forceinline__ void cp_commit() { asm volatile("cp.async.commit_group;" ::: "memory"); }
__device__ __forceinline__ void ldsm_x4(uint32_t& r0, uint32_t& r1, uint32_t& r2, uint32_t& r3,
                                        uint32_t addr) {
    asm volatile("ldmatrix.sync.aligned.m8n8.x4.shared.b16 {%0,%1,%2,%3}, [%4];"
        : "=r"(r0), "=r"(r1), "=r"(r2), "=r"(r3) : "r"(addr));
}
__device__ __forceinline__ void ldsm_x2(uint32_t& r0, uint32_t& r1, uint32_t addr) {
    asm volatile("ldmatrix.sync.aligned.m8n8.x2.shared.b16 {%0,%1}, [%2];"
        : "=r"(r0), "=r"(r1) : "r"(addr));
}
__device__ __forceinline__ void mma16816(float* c, const uint32_t* a, const uint32_t* b) {
    asm volatile("mma.sync.aligned.m16n8k16.row.col.f32.bf16.bf16.f32 "
        "{%0,%1,%2,%3}, {%4,%5,%6,%7}, {%8,%9}, {%0,%1,%2,%3};"
        : "+f"(c[0]), "+f"(c[1]), "+f"(c[2]), "+f"(c[3])
        : "r"(a[0]), "r"(a[1]), "r"(a[2]), "r"(a[3]), "r"(b[0]), "r"(b[1]));
}
__device__ __forceinline__ uint32_t pack2(float x, float y, uint32_t& lo) {
    __nv_bfloat16 hx = __float2bfloat16(x), hy = __float2bfloat16(y);
    __nv_bfloat16 lx = __float2bfloat16(x - __bfloat162float(hx));
    __nv_bfloat16 ly = __float2bfloat16(y - __bfloat162float(hy));
    lo = (uint32_t)__bfloat16_as_ushort(lx) | ((uint32_t)__bfloat16_as_ushort(ly) << 16);
    return (uint32_t)__bfloat16_as_ushort(hx) | ((uint32_t)__bfloat16_as_ushort(hy) << 16);
}

// ============================================================
// norms (bitwise-matching XLA warp row-reduce) + flag reset
// ============================================================
__device__ __forceinline__ float row_sumsq(const float* __restrict__ src, int w, int lane) {
    float4 v = reinterpret_cast<const float4*>(src + (size_t)w * D_DIM)[lane];
    float s = __fmul_rn(v.x, v.x);
    s = __fadd_rn(s, __fmul_rn(v.y, v.y));
    s = __fadd_rn(s, __fmul_rn(v.z, v.z));
    s = __fadd_rn(s, __fmul_rn(v.w, v.w));
    #pragma unroll
    for (int o = 16; o > 0; o >>= 1)
        s = __fadd_rn(s, __shfl_down_sync(0xffffffffu, s, o));
    return s;
}
__global__ void enorm_kernel(const float* __restrict__ E) {
    if (blockIdx.x == 0 && threadIdx.x == 0) g_flagCount = 0;
    int w = (int)((blockIdx.x * (size_t)blockDim.x + threadIdx.x) >> 5);
    int lane = threadIdx.x & 31;
    if (w >= K_CODES) return;
    float s = row_sumsq(E, w, lane);
    if (lane == 0) g_enorm[w] = s;
}
__global__ void cnorm_kernel(const float* __restrict__ X) {
    int w = (int)((blockIdx.x * (size_t)blockDim.x + threadIdx.x) >> 5);
    int lane = threadIdx.x & 31;
    if (w >= N_ROWS) return;
    float s = row_sumsq(X, w, lane);
    if (lane == 0) g_cnorm[w] = s;
}

// ============================================================
// B' prep: per code n, [b1 | b2], k-contiguous (512B/row)
// ============================================================
__global__ void eprep_kernel(const float* __restrict__ E) {
    int p = blockIdx.x * blockDim.x + threadIdx.x;   // pair id
    if (p >= K_CODES * 64) return;
    int n = p >> 6, cp = (p & 63) * 2;
    float2 v = *reinterpret_cast<const float2*>(E + (size_t)n * D_DIM + cp);
    uint32_t lo, hi = pack2(v.x, v.y, lo);
    uint32_t* row = reinterpret_cast<uint32_t*>(g_B + (size_t)n * 256);
    row[(cp) >> 1]       = hi;
    row[(128 + cp) >> 1] = lo;
}

// ============================================================
// Main mma.sync argmin kernel.
// 256 thr, 128 rows/CTA, 2 CTAs/SM (smem 100KB, regs capped 128).
// Virtual K=384 via chunk-indexed bases: per N-tile (64 codes),
// 3 chunks of 128k: kc=0 a1*b1, kc=1 a1*b2, kc=2 a2*b1.
// warp grid 2(M)x4(N), warp tile 64x16, epilogue every 3rd chunk.
// ============================================================
__global__ void __launch_bounds__(256, 2)
mma_argmin_kernel(const float* __restrict__ X) {
    extern __shared__ char sm[];
    const uint32_t smb = smem_u32(sm);
    const int tid = threadIdx.x;
    const int w = tid >> 5, lane = tid & 31;
    const int wm = w & 1, wn = w >> 1;
    const int tg = lane >> 2, tig = lane & 3;
    const int rowBase = blockIdx.x * 128;

    // ---- build A' = [a1 | a2] in smem (256 cols, padded stride) ----
    for (int p = tid; p < 128 * 64; p += 256) {
        int m = p >> 6, cp = (p & 63) * 2;
        float2 v = *reinterpret_cast<const float2*>(X + (size_t)(rowBase + m) * D_DIM + cp);
        uint32_t lo, hi = pack2(v.x, v.y, lo);
        char* rp = sm + (size_t)m * AS_STRIDE_B;
        *reinterpret_cast<uint32_t*>(rp + cp * 2)         = hi;
        *reinterpret_cast<uint32_t*>(rp + (128 + cp) * 2) = lo;
    }

    // per-owned-row |x|^2
    float cn[4][2];
    #pragma unroll
    for (int mt = 0; mt < 4; ++mt)
        #pragma unroll
        for (int h = 0; h < 2; ++h)
            cn[mt][h] = g_cnorm[rowBase + wm * 64 + mt * 16 + tg + h * 8];

    float m1[4][2], m2[4][2];
    int   i1[4][2];
    #pragma unroll
    for (int mt = 0; mt < 4; ++mt)
        #pragma unroll
        for (int h = 0; h < 2; ++h) { m1[mt][h] = 3.4e38f; m2[mt][h] = 3.4e38f; i1[mt][h] = 0; }

    float acc[4][2][4];
    #pragma unroll
    for (int mt = 0; mt < 4; ++mt)
        #pragma unroll
        for (int nt = 0; nt < 2; ++nt)
            #pragma unroll
            for (int q = 0; q < 4; ++q) acc[mt][nt][q] = 0.f;

    // chunk c: N-tile NT=c/3 (codes NT*64..+64), kc=c%3.
    // B real col base: {0,128,0}[kc]; A col base: {0,0,128}[kc].
    auto load_chunk = [&](int buf, int c) {
        int NT = c / 3, kc = c % 3;
        int bcol = (kc == 1) ? 128 : 0;
        uint32_t dbase = smb + SM_B_OFF + (uint32_t)buf * SM_B_BYTES;
        const char* gb = reinterpret_cast<const char*>(g_B);
        for (int i = tid; i < 1024; i += 256) {
            int n = i >> 4, seg = i & 15;          // 64 rows x 16 x 16B
            cp16(dbase + (uint32_t)n * BS_STRIDE_B + seg * 16,
                 gb + (size_t)(NT * 64 + n) * 512 + bcol * 2 + seg * 16);
        }
    };

    load_chunk(0, 0); cp_commit();
    load_chunk(1, 1); cp_commit();

    for (int c = 0; c < 48; ++c) {
        const int kc = c % 3, NT = c / 3;
        asm volatile("cp.async.wait_group 1;" ::: "memory");
        __syncthreads();                       // chunk c ready + (first iter) A ready
        const int buf = c & 1;
        const uint32_t bbase = smb + SM_B_OFF + (uint32_t)buf * SM_B_BYTES;
        const int acol = (kc == 2) ? 128 : 0;  // A col base for this chunk

        #pragma unroll
        for (int ks = 0; ks < 8; ++ks) {
            uint32_t a[4][4];
            #pragma unroll
            for (int mt = 0; mt < 4; ++mt) {
                int row = wm * 64 + mt * 16 + (lane & 15);
                uint32_t addr = smb + (uint32_t)row * AS_STRIDE_B
                              + (uint32_t)(acol + ks * 16 + (lane >> 4) * 8) * 2;
                ldsm_x4(a[mt][0], a[mt][1], a[mt][2], a[mt][3], addr);
            }
            uint32_t b[2][2];
            #pragma unroll
            for (int nt = 0; nt < 2; ++nt) {
                int n = wn * 16 + nt * 8 + (lane & 7);
                int kb = ks * 16 + ((lane >> 3) & 1) * 8;
                ldsm_x2(b[nt][0], b[nt][1],
                        bbase + (uint32_t)n * BS_STRIDE_B + (uint32_t)kb * 2);
            }
            #pragma unroll
            for (int mt = 0; mt < 4; ++mt)
                #pragma unroll
                for (int nt = 0; nt < 2; ++nt)
                    mma16816(acc[mt][nt], a[mt], b[nt]);
        }

        __syncthreads();                       // all warps done reading buf
        if (c + 2 < 48) load_chunk(buf, c + 2);
        cp_commit();

        if (kc == 2) {                         // N-tile NT complete -> epilogue
            float en[2][2];
            const int kbase = NT * 64 + wn * 16;
            #pragma unroll
            for (int nt = 0; nt < 2; ++nt)
                #pragma unroll
                for (int cc = 0; cc < 2; ++cc)
                    en[nt][cc] = g_enorm[kbase + nt * 8 + 2 * tig + cc];
            #pragma unroll
            for (int mt = 0; mt < 4; ++mt)
                #pragma unroll
                for (int h = 0; h < 2; ++h) {
                    float base = cn[mt][h];
                    #pragma unroll
                    for (int nt = 0; nt < 2; ++nt)
                        #pragma unroll
                        for (int cc = 0; cc < 2; ++cc) {
                            float d = fmaf(-2.f, acc[mt][nt][h * 2 + cc], base + en[nt][cc]);
                            int kk = kbase + nt * 8 + 2 * tig + cc;
                            if (d < m1[mt][h]) {
                                m2[mt][h] = m1[mt][h]; m1[mt][h] = d; i1[mt][h] = kk;
                            } else if (d < m2[mt][h]) m2[mt][h] = d;
                        }
                }
            #pragma unroll
            for (int mt = 0; mt < 4; ++mt)
                #pragma unroll
                for (int nt = 0; nt < 2; ++nt)
                    #pragma unroll
                    for (int q = 0; q < 4; ++q) acc[mt][nt][q] = 0.f;
        }
    }

    // ---- cross-thread merge: 16 contributors per row (reuse A region) ----
    // No index tie-break needed: approx tie => gap==0 < TAU => flagged =>
    // resolved by the exact (tie-correct) fixup.
    __syncthreads();
    float* redM1 = reinterpret_cast<float*>(sm);          // [128][16]
    float* redM2 = redM1 + 2048;
    int*   redI  = reinterpret_cast<int*>(redM2 + 2048);
    #pragma unroll
    for (int mt = 0; mt < 4; ++mt)
        #pragma unroll
        for (int h = 0; h < 2; ++h) {
            int r = wm * 64 + mt * 16 + tg + h * 8;
            int q = wn * 4 + tig;
            redM1[r * 16 + q] = m1[mt][h];
            redM2[r * 16 + q] = m2[mt][h];
            redI [r * 16 + q] = i1[mt][h];
        }
    __syncthreads();

    float dmin = 0.f;
    if (tid < 128) {
        float M1 = redM1[tid * 16], M2 = redM2[tid * 16];
        int   I  = redI[tid * 16];
        #pragma unroll
        for (int q = 1; q < 16; ++q) {
            float a1v = redM1[tid * 16 + q];
            if (a1v < M1) {
                M2 = fminf(M1, redM2[tid * 16 + q]);
                M1 = a1v;
                I  = redI[tid * 16 + q];
            } else {
                M2 = fminf(M2, a1v);
            }
        }
        int row = rowBase + tid;
        g_idx[row] = I;
        if (M2 - M1 < TAU) {
            int f = atomicAdd(&g_flagCount, 1);
            if (f < FLAG_CAP) g_flagRows[f] = row;
        }
        dmin = M1;
    }
    __syncthreads();

    float* rsum = reinterpret_cast<float*>(sm);
    if (tid < 128) rsum[tid] = dmin;
    __syncthreads();
    for (int off = 64; off > 0; off >>= 1) {
        if (tid < off) rsum[tid] += rsum[tid + off];
        __syncthreads();
    }
    if (tid == 0) g_lossPartial[blockIdx.x] = rsum[0];
}

// ============================================================
// exact fixup for flagged (near-tie) rows: bitwise ref pipeline.
// Reduction carries EXPLICIT index tie-break (jnp.argmin first-min).
// ============================================================
__global__ void fixup_kernel(const float* __restrict__ X, const float* __restrict__ E) {
    __shared__ float xs[128];
    __shared__ float rv[256];
    __shared__ int   ri[256];
    int nf = g_flagCount;
    if (nf > FLAG_CAP) nf = FLAG_CAP;
    for (int f = blockIdx.x; f < nf; f += gridDim.x) {
        int row = g_flagRows[f];
        if (threadIdx.x < 128) xs[threadIdx.x] = X[(size_t)row * D_DIM + threadIdx.x];
        __syncthreads();
        float cnv = g_cnorm[row];
        float bv = 3.4e38f;
        int   bi = 0;
        #pragma unroll
        for (int k0 = 0; k0 < 4; ++k0) {
            int k = threadIdx.x * 4 + k0;          // ascending per thread
            const float* er = E + (size_t)k * D_DIM;
            float acc = 0.f;
            for (int d = 0; d < D_DIM; ++d) acc = fmaf(xs[d], er[d], acc);
            float t1 = __fadd_rn(cnv, g_enorm[k]);
            float dd = __fadd_rn(t1, -__fmul_rn(2.0f, acc));
            if (dd < bv) { bv = dd; bi = k; }
        }
        rv[threadIdx.x] = bv;
        ri[threadIdx.x] = bi;
        __syncthreads();
        for (int off = 128; off > 0; off >>= 1) {
            if (threadIdx.x < off) {
                float rvr = rv[threadIdx.x + off];
                int   rir = ri[threadIdx.x + off];
                if (rvr < rv[threadIdx.x] ||
                    (rvr == rv[threadIdx.x] && rir < ri[threadIdx.x])) {
                    rv[threadIdx.x] = rvr;
                    ri[threadIdx.x] = rir;
                }
            }
            __syncthreads();
        }
        if (threadIdx.x == 0) g_idx[row] = ri[0];
        __syncthreads();
    }
}

// ============================================================
// loss = 1.25 * sum(dmin) / (N*D)
// ============================================================
__global__ void loss_kernel(float* __restrict__ out) {
    __shared__ float smr[256];
    float s = 0.f;
    for (int i = threadIdx.x; i < N_ROWS / 128; i += 256) s += g_lossPartial[i];
    smr[threadIdx.x] = s;
    __syncthreads();
    for (int off = 128; off > 0; off >>= 1) {
        if (threadIdx.x < off) smr[threadIdx.x] += smr[threadIdx.x + off];
        __syncthreads();
    }
    if (threadIdx.x == 0)
        out[0] = smr[0] * (1.25f / ((float)N_ROWS * (float)D_DIM));
}

// ============================================================
// writer: quantized_st = fl(c + fl(e[idx]-c)) + one-hot encodings
// ============================================================
__global__ void __launch_bounds__(256)
writer_kernel(const float* __restrict__ X, const float* __restrict__ E,
              float* __restrict__ out) {
    int warp = (int)((blockIdx.x * (size_t)blockDim.x + threadIdx.x) >> 5);
    int lane = threadIdx.x & 31;
    if (warp >= N_ROWS) return;
    int idx = g_idx[warp];

    const float* er = E + (size_t)idx * D_DIM;
    const float* xr = X + (size_t)warp * D_DIM;
    float* q = out + 1 + (size_t)warp * D_DIM;
    #pragma unroll
    for (int i = 0; i < 4; i++) {
        int d = lane + 32 * i;
        float c = xr[d];
        float e = er[d];
        q[d] = __fadd_rn(c, __fadd_rn(e, -c));
    }
    float* enc = out + 1 + (size_t)N_ROWS * D_DIM + (size_t)warp * K_CODES;
    #pragma unroll
    for (int i = 0; i < 32; i++) {
        int k = lane + 32 * i;
        enc[k] = (k == idx) ? 1.0f : 0.0f;
    }
}

// ============================================================
extern "C" void kernel_launch(void* const* d_in, const int* in_sizes, int n_in,
                              void* d_out, int out_size) {
    const float* X = (const float*)d_in[0];
    const float* E = (const float*)d_in[1];
    float* out = (float*)d_out;

    cudaFuncSetAttribute(mma_argmin_kernel,
                         cudaFuncAttributeMaxDynamicSharedMemorySize, SM_TOTAL);

    enorm_kernel<<<K_CODES * 32 / 256, 256>>>(E);
    cnorm_kernel<<<N_ROWS * 32 / 256, 256>>>(X);
    eprep_kernel<<<(K_CODES * 64) / 256, 256>>>(E);
    mma_argmin_kernel<<<N_ROWS / 128, 256, SM_TOTAL>>>(X);
    fixup_kernel<<<256, 256>>>(X, E);
    loss_kernel<<<1, 256>>>(out);
    writer_kernel<<<N_ROWS / 8, 256>>>(X, E, out);
}